// round 1
// baseline (speedup 1.0000x reference)
#include <cuda_runtime.h>
#include <cstdint>
#include <cstddef>

#define Lq 2048
#define Hh 16
#define Cc 64
#define Bb 2

// Output layout: [context (B,L,H*C)] [scores (B,H,L,L)] [weights (B,H,L,L)]
#define OFF_S  ((size_t)Bb * Lq * Hh * Cc)                 // 4194304
#define NSCORE ((size_t)Bb * Hh * Lq * Lq)                 // 134217728
#define OFF_W  (OFF_S + NSCORE)

__device__ int g_mask_kind;  // 0 = u8/bool, 1 = int32, 2 = float32

// ---------------------------------------------------------------------------
// Mask dtype detection: bool serialization is ambiguous; classify from the
// first 1KiB of bits. Random 0/1 bytes cannot alias the int32 or f32 patterns
// over 256 words (prob ~8^-256).
// ---------------------------------------------------------------------------
__global__ void detect_mask_kernel(const void* __restrict__ m) {
    if (threadIdx.x == 0 && blockIdx.x == 0) {
        const unsigned int* w = (const unsigned int*)m;
        bool i32 = true, f32 = true;
        for (int t = 0; t < 256; t++) {
            unsigned int v = w[t];
            if (v > 1u) i32 = false;
            if (v != 0u && v != 0x3F800000u) f32 = false;
        }
        g_mask_kind = i32 ? 1 : (f32 ? 2 : 0);
    }
}

// ---------------------------------------------------------------------------
// Kernel 1: scores[b,h,i,j] = sum_c Q[b,i,h,c]*K[b,j,h,c] + edge[h,i,j]
// 64x64 output tile per block, K=C=64 in one shot. 16x16 threads, 4x4 regs.
// ---------------------------------------------------------------------------
__global__ __launch_bounds__(256) void scores_kernel(
    const float* __restrict__ q, const float* __restrict__ k,
    const float* __restrict__ edge, float* __restrict__ out_scores) {
    const int bh = blockIdx.z;
    const int b = bh >> 4, h = bh & 15;
    const int i0 = blockIdx.y << 6;
    const int j0 = blockIdx.x << 6;

    __shared__ float Qs[64][68];   // [i][c]   (read as warp-broadcast)
    __shared__ float Ks[64][65];   // [c][j]   (transposed; odd pad -> <=2-way)

    const int tx = threadIdx.x, ty = threadIdx.y;
    const int tid = ty * 16 + tx;
    const int lrow = tid >> 4;     // 0..15
    const int lc4  = tid & 15;     // float4 column

#pragma unroll
    for (int r = 0; r < 4; r++) {
        const int row = lrow + r * 16;
        const float4 vq = *(const float4*)(q +
            ((size_t)(b * Lq + i0 + row) * Hh + h) * Cc + lc4 * 4);
        *(float4*)&Qs[row][lc4 * 4] = vq;
        const float4 vk = *(const float4*)(k +
            ((size_t)(b * Lq + j0 + row) * Hh + h) * Cc + lc4 * 4);
        Ks[lc4 * 4 + 0][row] = vk.x;
        Ks[lc4 * 4 + 1][row] = vk.y;
        Ks[lc4 * 4 + 2][row] = vk.z;
        Ks[lc4 * 4 + 3][row] = vk.w;
    }
    __syncthreads();

    float acc[4][4] = {};
#pragma unroll 8
    for (int c = 0; c < 64; c++) {
        float qr[4], kr[4];
#pragma unroll
        for (int ii = 0; ii < 4; ii++) qr[ii] = Qs[ty * 4 + ii][c];
#pragma unroll
        for (int jj = 0; jj < 4; jj++) kr[jj] = Ks[c][tx * 4 + jj];
#pragma unroll
        for (int ii = 0; ii < 4; ii++)
#pragma unroll
            for (int jj = 0; jj < 4; jj++)
                acc[ii][jj] += qr[ii] * kr[jj];
    }

#pragma unroll
    for (int ii = 0; ii < 4; ii++) {
        const int i = i0 + ty * 4 + ii;
        const size_t eoff = ((size_t)h * Lq + i) * Lq + j0 + tx * 4;
        const size_t soff = ((size_t)bh * Lq + i) * Lq + j0 + tx * 4;
        const float4 e = *(const float4*)(edge + eoff);
        float4 o;
        o.x = acc[ii][0] + e.x;
        o.y = acc[ii][1] + e.y;
        o.z = acc[ii][2] + e.z;
        o.w = acc[ii][3] + e.w;
        *(float4*)(out_scores + soff) = o;
    }
}

// ---------------------------------------------------------------------------
// Kernel 2: masked softmax over the last dim.
//   x = mask ? scores/8 : -1e18 ; w = softmax(x) * mask
// One 256-thread block per row (b,h,i); 8 elems/thread.
// ---------------------------------------------------------------------------
__global__ __launch_bounds__(256) void softmax_kernel(
    const float* __restrict__ scores, const void* __restrict__ mask,
    float* __restrict__ wout) {
    const int row = blockIdx.x;          // bh*L + i
    const int bh = row >> 11;
    const int i  = row & (Lq - 1);
    const int b  = bh >> 4;
    const size_t soff = (size_t)row * Lq;
    const size_t moff = ((size_t)(b * Lq + i)) * Lq;
    const int tid = threadIdx.x;
    const int kind = g_mask_kind;

    float x[8], mb[8];
#pragma unroll
    for (int t = 0; t < 8; t++) {
        const int j = t * 256 + tid;
        const float s = scores[soff + j];
        bool m;
        if (kind == 1)      m = ((const int*)mask)[moff + j] != 0;
        else if (kind == 2) m = ((const float*)mask)[moff + j] != 0.0f;
        else                m = ((const unsigned char*)mask)[moff + j] != 0;
        mb[t] = m ? 1.0f : 0.0f;
        x[t]  = m ? s * 0.125f : -1e18f;
    }

    float mx = x[0];
#pragma unroll
    for (int t = 1; t < 8; t++) mx = fmaxf(mx, x[t]);
#pragma unroll
    for (int o = 16; o; o >>= 1) mx = fmaxf(mx, __shfl_xor_sync(0xffffffffu, mx, o));

    __shared__ float red_max[8];
    __shared__ float red_sum[8];
    if ((tid & 31) == 0) red_max[tid >> 5] = mx;
    __syncthreads();
    mx = red_max[0];
#pragma unroll
    for (int wi = 1; wi < 8; wi++) mx = fmaxf(mx, red_max[wi]);

    float e[8];
    float s = 0.0f;
#pragma unroll
    for (int t = 0; t < 8; t++) {
        e[t] = __expf(x[t] - mx);
        s += e[t];
    }
#pragma unroll
    for (int o = 16; o; o >>= 1) s += __shfl_xor_sync(0xffffffffu, s, o);
    if ((tid & 31) == 0) red_sum[tid >> 5] = s;
    __syncthreads();
    s = red_sum[0];
#pragma unroll
    for (int wi = 1; wi < 8; wi++) s += red_sum[wi];

    const float inv = 1.0f / s;
#pragma unroll
    for (int t = 0; t < 8; t++) {
        const int j = t * 256 + tid;
        wout[soff + j] = e[t] * inv * mb[t];
    }
}

// ---------------------------------------------------------------------------
// Kernel 3: ctx[b,i,h,c] = sum_j W[b,h,i,j] * V[b,j,h,c]
// 64(rows) x 64(all C) tile per block, 32 K-tiles of 64.
// ---------------------------------------------------------------------------
__global__ __launch_bounds__(256) void av_kernel(
    const float* __restrict__ w, const float* __restrict__ v,
    float* __restrict__ ctx) {
    const int bh = blockIdx.y;
    const int b = bh >> 4, h = bh & 15;
    const int i0 = blockIdx.x << 6;

    __shared__ float Ws[64][68];   // [i][j]  (read broadcast-ish)
    __shared__ float Vs[64][68];   // [j][c]  (read as aligned float4)

    const int tx = threadIdx.x, ty = threadIdx.y;
    const int tid = ty * 16 + tx;
    const int lrow = tid >> 4, lc4 = tid & 15;

    float4 acc[4] = {};

    for (int j0 = 0; j0 < Lq; j0 += 64) {
#pragma unroll
        for (int r = 0; r < 4; r++) {
            const int row = lrow + r * 16;
            *(float4*)&Ws[row][lc4 * 4] = *(const float4*)(w +
                ((size_t)bh * Lq + i0 + row) * Lq + j0 + lc4 * 4);
            *(float4*)&Vs[row][lc4 * 4] = *(const float4*)(v +
                ((size_t)(b * Lq + j0 + row) * Hh + h) * Cc + lc4 * 4);
        }
        __syncthreads();
#pragma unroll 16
        for (int j = 0; j < 64; j++) {
            const float4 vv = *(const float4*)&Vs[j][tx * 4];
#pragma unroll
            for (int ii = 0; ii < 4; ii++) {
                const float wr = Ws[ty * 4 + ii][j];
                acc[ii].x += wr * vv.x;
                acc[ii].y += wr * vv.y;
                acc[ii].z += wr * vv.z;
                acc[ii].w += wr * vv.w;
            }
        }
        __syncthreads();
    }

#pragma unroll
    for (int ii = 0; ii < 4; ii++) {
        const int i = i0 + ty * 4 + ii;
        *(float4*)(ctx + ((size_t)(b * Lq + i) * Hh + h) * Cc + tx * 4) = acc[ii];
    }
}

// ---------------------------------------------------------------------------
extern "C" void kernel_launch(void* const* d_in, const int* in_sizes, int n_in,
                              void* d_out, int out_size) {
    (void)in_sizes; (void)n_in; (void)out_size;
    const float* q    = (const float*)d_in[0];
    const float* k    = (const float*)d_in[1];
    const float* v    = (const float*)d_in[2];
    const void*  mask = d_in[3];
    const float* edge = (const float*)d_in[4];

    float* out     = (float*)d_out;
    float* ctx     = out;                 // (B, L, H*C)
    float* scores  = out + OFF_S;         // (B, H, L, L)
    float* weights = out + OFF_W;         // (B, H, L, L)

    detect_mask_kernel<<<1, 32>>>(mask);

    {
        dim3 grid(Lq / 64, Lq / 64, Bb * Hh);
        dim3 block(16, 16);
        scores_kernel<<<grid, block>>>(q, k, edge, scores);
    }
    {
        dim3 grid(Bb * Hh * Lq);
        softmax_kernel<<<grid, 256>>>(scores, mask, weights);
    }
    {
        dim3 grid(Lq / 64, Bb * Hh);
        dim3 block(16, 16);
        av_kernel<<<grid, block>>>(weights, v, ctx);
    }
}

// round 2
// speedup vs baseline: 1.0267x; 1.0267x over previous
#include <cuda_runtime.h>
#include <cstdint>
#include <cstddef>

#define Lq 2048
#define Hh 16
#define Cc 64
#define Bb 2

// Output layout: [context (B,L,H*C)] [scores (B,H,L,L)] [weights (B,H,L,L)]
#define OFF_S  ((size_t)Bb * Lq * Hh * Cc)
#define NSCORE ((size_t)Bb * Hh * Lq * Lq)
#define OFF_W  (OFF_S + NSCORE)

#define QK_PAD 132                 // 128 + 4 floats row pad (write scatter -> 2-way max)
#define SMEM_SCORES (2 * 64 * QK_PAD * 4)          // Qt + Kt, bytes
#define SMEM_AV     ((64 * QK_PAD + 64 * 68) * 4)  // Wt + Vs, bytes

__device__ int g_mask_kind;  // 0 = u8/bool, 1 = int32, 2 = float32

// ---------------------------------------------------------------------------
__global__ void detect_mask_kernel(const void* __restrict__ m) {
    if (threadIdx.x == 0 && blockIdx.x == 0) {
        const unsigned int* w = (const unsigned int*)m;
        bool i32 = true, f32 = true;
        for (int t = 0; t < 256; t++) {
            unsigned int v = w[t];
            if (v > 1u) i32 = false;
            if (v != 0u && v != 0x3F800000u) f32 = false;
        }
        g_mask_kind = i32 ? 1 : (f32 ? 2 : 0);
    }
}

// ---------------------------------------------------------------------------
// Kernel 1: scores[b,h,i,j] = sum_c Q[b,i,h,c]*K[b,j,h,c] + edge[h,i,j]
// 128x128 tile, K=64 single pass, 256 threads, 8x8 regs (4+4 split columns).
// ---------------------------------------------------------------------------
__global__ __launch_bounds__(256, 2) void scores_kernel(
    const float* __restrict__ q, const float* __restrict__ k,
    const float* __restrict__ edge, float* __restrict__ out_scores) {
    extern __shared__ float sm[];
    float* Qt = sm;                    // [64][QK_PAD]  c-major: Qt[c][i]
    float* Kt = sm + 64 * QK_PAD;      // [64][QK_PAD]  c-major: Kt[c][j]

    const int bh = blockIdx.z;
    const int b = bh >> 4, h = bh & 15;
    const int i0 = blockIdx.y << 7;
    const int j0 = blockIdx.x << 7;
    const int tx = threadIdx.x, ty = threadIdx.y;
    const int tid = ty * 16 + tx;

#pragma unroll
    for (int r = 0; r < 8; r++) {
        const int idx = r * 256 + tid;
        const int row = idx >> 4;            // 0..127
        const int c4  = (idx & 15) * 4;      // 0..60
        const float4 vq = *(const float4*)(q +
            ((size_t)(b * Lq + i0 + row) * Hh + h) * Cc + c4);
        Qt[(c4 + 0) * QK_PAD + row] = vq.x;
        Qt[(c4 + 1) * QK_PAD + row] = vq.y;
        Qt[(c4 + 2) * QK_PAD + row] = vq.z;
        Qt[(c4 + 3) * QK_PAD + row] = vq.w;
        const float4 vk = *(const float4*)(k +
            ((size_t)(b * Lq + j0 + row) * Hh + h) * Cc + c4);
        Kt[(c4 + 0) * QK_PAD + row] = vk.x;
        Kt[(c4 + 1) * QK_PAD + row] = vk.y;
        Kt[(c4 + 2) * QK_PAD + row] = vk.z;
        Kt[(c4 + 3) * QK_PAD + row] = vk.w;
    }
    __syncthreads();

    const int ia = ty * 4, ib = 64 + ty * 4;
    const int ja = tx * 4, jb = 64 + tx * 4;
    float acc[8][8] = {};

#pragma unroll 8
    for (int c = 0; c < 64; c++) {
        const float4 a0 = *(const float4*)&Qt[c * QK_PAD + ia];
        const float4 a1 = *(const float4*)&Qt[c * QK_PAD + ib];
        const float4 b0 = *(const float4*)&Kt[c * QK_PAD + ja];
        const float4 b1 = *(const float4*)&Kt[c * QK_PAD + jb];
        const float ar[8] = {a0.x, a0.y, a0.z, a0.w, a1.x, a1.y, a1.z, a1.w};
        const float br[8] = {b0.x, b0.y, b0.z, b0.w, b1.x, b1.y, b1.z, b1.w};
#pragma unroll
        for (int ii = 0; ii < 8; ii++)
#pragma unroll
            for (int jj = 0; jj < 8; jj++)
                acc[ii][jj] += ar[ii] * br[jj];
    }

#pragma unroll
    for (int ii = 0; ii < 8; ii++) {
        const int i = i0 + ((ii < 4) ? (ty * 4 + ii) : (64 + ty * 4 + ii - 4));
        const size_t ebase = ((size_t)h * Lq + i) * Lq + j0;
        const size_t sbase = ((size_t)bh * Lq + i) * Lq + j0;
        const float4 e0 = *(const float4*)(edge + ebase + ja);
        const float4 e1 = *(const float4*)(edge + ebase + jb);
        float4 o0, o1;
        o0.x = acc[ii][0] + e0.x; o0.y = acc[ii][1] + e0.y;
        o0.z = acc[ii][2] + e0.z; o0.w = acc[ii][3] + e0.w;
        o1.x = acc[ii][4] + e1.x; o1.y = acc[ii][5] + e1.y;
        o1.z = acc[ii][6] + e1.z; o1.w = acc[ii][7] + e1.w;
        *(float4*)(out_scores + sbase + ja) = o0;
        *(float4*)(out_scores + sbase + jb) = o1;
    }
}

// ---------------------------------------------------------------------------
// Kernel 2: masked softmax. One 256-thread block per (b,h,i) row; float4/int4.
// ---------------------------------------------------------------------------
__global__ __launch_bounds__(256) void softmax_kernel(
    const float* __restrict__ scores, const void* __restrict__ mask,
    float* __restrict__ wout) {
    const int row = blockIdx.x;
    const int bh = row >> 11;
    const int i  = row & (Lq - 1);
    const int b  = bh >> 4;
    const size_t soff = (size_t)row * Lq;
    const size_t moff = ((size_t)(b * Lq + i)) * Lq;
    const int tid = threadIdx.x;
    const int kind = g_mask_kind;

    const float4* sp = (const float4*)(scores + soff);
    const float4 s0 = sp[tid];
    const float4 s1 = sp[256 + tid];

    float mb[8];
    if (kind == 1) {
        const int4* mp = (const int4*)((const int*)mask + moff);
        const int4 m0 = mp[tid], m1 = mp[256 + tid];
        mb[0] = m0.x ? 1.f : 0.f; mb[1] = m0.y ? 1.f : 0.f;
        mb[2] = m0.z ? 1.f : 0.f; mb[3] = m0.w ? 1.f : 0.f;
        mb[4] = m1.x ? 1.f : 0.f; mb[5] = m1.y ? 1.f : 0.f;
        mb[6] = m1.z ? 1.f : 0.f; mb[7] = m1.w ? 1.f : 0.f;
    } else if (kind == 2) {
        const float4* mp = (const float4*)((const float*)mask + moff);
        const float4 m0 = mp[tid], m1 = mp[256 + tid];
        mb[0] = (m0.x != 0.f); mb[1] = (m0.y != 0.f);
        mb[2] = (m0.z != 0.f); mb[3] = (m0.w != 0.f);
        mb[4] = (m1.x != 0.f); mb[5] = (m1.y != 0.f);
        mb[6] = (m1.z != 0.f); mb[7] = (m1.w != 0.f);
    } else {
        const uchar4* mp = (const uchar4*)((const unsigned char*)mask + moff);
        const uchar4 m0 = mp[tid], m1 = mp[256 + tid];
        mb[0] = m0.x ? 1.f : 0.f; mb[1] = m0.y ? 1.f : 0.f;
        mb[2] = m0.z ? 1.f : 0.f; mb[3] = m0.w ? 1.f : 0.f;
        mb[4] = m1.x ? 1.f : 0.f; mb[5] = m1.y ? 1.f : 0.f;
        mb[6] = m1.z ? 1.f : 0.f; mb[7] = m1.w ? 1.f : 0.f;
    }

    const float sv[8] = {s0.x, s0.y, s0.z, s0.w, s1.x, s1.y, s1.z, s1.w};
    float x[8];
#pragma unroll
    for (int t = 0; t < 8; t++)
        x[t] = (mb[t] != 0.f) ? sv[t] * 0.125f : -1e18f;

    float mx = x[0];
#pragma unroll
    for (int t = 1; t < 8; t++) mx = fmaxf(mx, x[t]);
#pragma unroll
    for (int o = 16; o; o >>= 1) mx = fmaxf(mx, __shfl_xor_sync(0xffffffffu, mx, o));

    __shared__ float red_max[8];
    __shared__ float red_sum[8];
    if ((tid & 31) == 0) red_max[tid >> 5] = mx;
    __syncthreads();
    mx = red_max[0];
#pragma unroll
    for (int wi = 1; wi < 8; wi++) mx = fmaxf(mx, red_max[wi]);

    float e[8];
    float s = 0.0f;
#pragma unroll
    for (int t = 0; t < 8; t++) {
        e[t] = __expf(x[t] - mx);
        s += e[t];
    }
#pragma unroll
    for (int o = 16; o; o >>= 1) s += __shfl_xor_sync(0xffffffffu, s, o);
    if ((tid & 31) == 0) red_sum[tid >> 5] = s;
    __syncthreads();
    s = red_sum[0];
#pragma unroll
    for (int wi = 1; wi < 8; wi++) s += red_sum[wi];

    const float inv = 1.0f / s;
    float4 w0, w1;
    w0.x = e[0] * inv * mb[0]; w0.y = e[1] * inv * mb[1];
    w0.z = e[2] * inv * mb[2]; w0.w = e[3] * inv * mb[3];
    w1.x = e[4] * inv * mb[4]; w1.y = e[5] * inv * mb[5];
    w1.z = e[6] * inv * mb[6]; w1.w = e[7] * inv * mb[7];
    float4* wp = (float4*)(wout + soff);
    wp[tid] = w0;
    wp[256 + tid] = w1;
}

// ---------------------------------------------------------------------------
// Kernel 3: ctx[b,i,h,c] = sum_j W[b,h,i,j] * V[b,j,h,c]
// 128(i) x 64(c) tile, K-tiles of 64, 256 threads, 8x4 regs (4+4 row split).
// ---------------------------------------------------------------------------
__global__ __launch_bounds__(256, 2) void av_kernel(
    const float* __restrict__ w, const float* __restrict__ v,
    float* __restrict__ ctx) {
    extern __shared__ float sm[];
    float* Wt = sm;                    // [64][QK_PAD]  j-major: Wt[j][i]
    float* Vs = sm + 64 * QK_PAD;      // [64][68]      Vs[j][c]

    const int bh = blockIdx.y;
    const int b = bh >> 4, h = bh & 15;
    const int i0 = blockIdx.x << 7;
    const int tx = threadIdx.x, ty = threadIdx.y;
    const int tid = ty * 16 + tx;

    float4 acc[8] = {};   // rows: ty*4+0..3 and 64+ty*4+0..3, cols tx*4..tx*4+3

    for (int j0 = 0; j0 < Lq; j0 += 64) {
        // W tile transpose: 128 i x 64 j
#pragma unroll
        for (int r = 0; r < 8; r++) {
            const int idx = r * 256 + tid;
            const int row = idx >> 4;          // i local
            const int j4  = (idx & 15) * 4;    // j local
            const float4 vw = *(const float4*)(w +
                ((size_t)bh * Lq + i0 + row) * Lq + j0 + j4);
            Wt[(j4 + 0) * QK_PAD + row] = vw.x;
            Wt[(j4 + 1) * QK_PAD + row] = vw.y;
            Wt[(j4 + 2) * QK_PAD + row] = vw.z;
            Wt[(j4 + 3) * QK_PAD + row] = vw.w;
        }
        // V tile straight copy: 64 j x 64 c
#pragma unroll
        for (int r = 0; r < 4; r++) {
            const int idx = r * 256 + tid;
            const int jj = idx >> 4;
            const int c4 = (idx & 15) * 4;
            *(float4*)&Vs[jj * 68 + c4] = *(const float4*)(v +
                ((size_t)(b * Lq + j0 + jj) * Hh + h) * Cc + c4);
        }
        __syncthreads();

#pragma unroll 8
        for (int j = 0; j < 64; j++) {
            const float4 a0 = *(const float4*)&Wt[j * QK_PAD + ty * 4];
            const float4 a1 = *(const float4*)&Wt[j * QK_PAD + 64 + ty * 4];
            const float4 vv = *(const float4*)&Vs[j * 68 + tx * 4];
            const float ar[8] = {a0.x, a0.y, a0.z, a0.w, a1.x, a1.y, a1.z, a1.w};
#pragma unroll
            for (int ii = 0; ii < 8; ii++) {
                acc[ii].x += ar[ii] * vv.x;
                acc[ii].y += ar[ii] * vv.y;
                acc[ii].z += ar[ii] * vv.z;
                acc[ii].w += ar[ii] * vv.w;
            }
        }
        __syncthreads();
    }

#pragma unroll
    for (int ii = 0; ii < 8; ii++) {
        const int i = i0 + ((ii < 4) ? (ty * 4 + ii) : (64 + ty * 4 + ii - 4));
        *(float4*)(ctx + ((size_t)(b * Lq + i) * Hh + h) * Cc + tx * 4) = acc[ii];
    }
}

// ---------------------------------------------------------------------------
extern "C" void kernel_launch(void* const* d_in, const int* in_sizes, int n_in,
                              void* d_out, int out_size) {
    (void)in_sizes; (void)n_in; (void)out_size;
    const float* q    = (const float*)d_in[0];
    const float* k    = (const float*)d_in[1];
    const float* v    = (const float*)d_in[2];
    const void*  mask = d_in[3];
    const float* edge = (const float*)d_in[4];

    float* out     = (float*)d_out;
    float* ctx     = out;
    float* scores  = out + OFF_S;
    float* weights = out + OFF_W;

    cudaFuncSetAttribute(scores_kernel,
        cudaFuncAttributeMaxDynamicSharedMemorySize, SMEM_SCORES);
    cudaFuncSetAttribute(av_kernel,
        cudaFuncAttributeMaxDynamicSharedMemorySize, SMEM_AV);

    detect_mask_kernel<<<1, 32>>>(mask);

    {
        dim3 grid(Lq / 128, Lq / 128, Bb * Hh);
        dim3 block(16, 16);
        scores_kernel<<<grid, block, SMEM_SCORES>>>(q, k, edge, scores);
    }
    {
        softmax_kernel<<<Bb * Hh * Lq, 256>>>(scores, mask, weights);
    }
    {
        dim3 grid(Lq / 128, Bb * Hh);
        dim3 block(16, 16);
        av_kernel<<<grid, block, SMEM_AV>>>(weights, v, ctx);
    }
}

// round 3
// speedup vs baseline: 1.6488x; 1.6059x over previous
#include <cuda_runtime.h>
#include <cstdint>
#include <cstddef>

#define Lq 2048
#define Hh 16
#define Cc 64
#define Bb 2

// Output layout: [context (B,L,H*C)] [scores (B,H,L,L)] [weights (B,H,L,L)]
#define OFF_S  ((size_t)Bb * Lq * Hh * Cc)
#define NSCORE ((size_t)Bb * Hh * Lq * Lq)
#define OFF_W  (OFF_S + NSCORE)

#define PAD 68
#define SMEM_SCORES (2 * 128 * PAD * 4)            // Qs + Ks
#define SMEM_AV     ((128 * PAD + 64 * PAD) * 4)   // Ws + Vt

__device__ int g_mask_kind;  // 0 = u8/bool, 1 = int32, 2 = float32

// ---------------------------------------------------------------------------
__global__ void detect_mask_kernel(const void* __restrict__ m) {
    if (threadIdx.x == 0 && blockIdx.x == 0) {
        const unsigned int* w = (const unsigned int*)m;
        bool i32 = true, f32 = true;
        for (int t = 0; t < 256; t++) {
            unsigned int v = w[t];
            if (v > 1u) i32 = false;
            if (v != 0u && v != 0x3F800000u) f32 = false;
        }
        g_mask_kind = i32 ? 1 : (f32 ? 2 : 0);
    }
}

// ---------------------------------------------------------------------------
__device__ __forceinline__ float f2tf(float x) {
    unsigned r;
    asm("cvt.rna.tf32.f32 %0, %1;" : "=r"(r) : "f"(x));
    return __uint_as_float(r);
}

__device__ __forceinline__ void mma_tf32(float (&d)[4], const float (&a)[4],
                                         float b0, float b1) {
    asm volatile(
        "mma.sync.aligned.m16n8k8.row.col.f32.tf32.tf32.f32 "
        "{%0,%1,%2,%3}, {%4,%5,%6,%7}, {%8,%9}, {%0,%1,%2,%3};"
        : "+f"(d[0]), "+f"(d[1]), "+f"(d[2]), "+f"(d[3])
        : "r"(__float_as_uint(a[0])), "r"(__float_as_uint(a[1])),
          "r"(__float_as_uint(a[2])), "r"(__float_as_uint(a[3])),
          "r"(__float_as_uint(b0)), "r"(__float_as_uint(b1)));
}

// ---------------------------------------------------------------------------
// Kernel 1: scores[b,h,i,j] = sum_c Q[b,i,h,c]*K[b,j,h,c] + edge[h,i,j]
// 128x128 CTA tile, K=64 one pass. 8 warps as 4(i) x 2(j); warp = 32i x 64j.
// TF32 mma m16n8k8. Qs[i][c], Ks[j][c] both natural row-major (pad 68).
// ---------------------------------------------------------------------------
__global__ __launch_bounds__(256) void scores_kernel(
    const float* __restrict__ q, const float* __restrict__ k,
    const float* __restrict__ edge, float* __restrict__ out_scores) {
    extern __shared__ float sm[];
    float* Qs = sm;                 // [128][PAD] : [i][c]
    float* Ks = sm + 128 * PAD;     // [128][PAD] : [j][c]

    const int bh = blockIdx.z;
    const int b = bh >> 4, h = bh & 15;
    const int i0 = blockIdx.y << 7;
    const int j0 = blockIdx.x << 7;
    const int tid = threadIdx.x;

#pragma unroll
    for (int r = 0; r < 8; r++) {
        const int idx = r * 256 + tid;
        const int row = idx >> 4;
        const int c4 = (idx & 15) * 4;
        const float4 vq = *(const float4*)(q +
            ((size_t)(b * Lq + i0 + row) * Hh + h) * Cc + c4);
        float* dstq = &Qs[row * PAD + c4];
        dstq[0] = f2tf(vq.x); dstq[1] = f2tf(vq.y);
        dstq[2] = f2tf(vq.z); dstq[3] = f2tf(vq.w);
        const float4 vk = *(const float4*)(k +
            ((size_t)(b * Lq + j0 + row) * Hh + h) * Cc + c4);
        float* dstk = &Ks[row * PAD + c4];
        dstk[0] = f2tf(vk.x); dstk[1] = f2tf(vk.y);
        dstk[2] = f2tf(vk.z); dstk[3] = f2tf(vk.w);
    }
    __syncthreads();

    const int warp = tid >> 5, lane = tid & 31;
    const int wi = warp >> 1, wj = warp & 1;     // 4 x 2
    const int ibase = wi * 32, jbase = wj * 64;
    const int gid = lane >> 2, qid = lane & 3;

    float acc[2][8][4] = {};

#pragma unroll
    for (int kk = 0; kk < 8; kk++) {
        const int k0 = kk * 8;
        float a[2][4];
#pragma unroll
        for (int m = 0; m < 2; m++) {
            const int rr = ibase + m * 16 + gid;
            a[m][0] = Qs[rr * PAD + k0 + qid];
            a[m][1] = Qs[(rr + 8) * PAD + k0 + qid];
            a[m][2] = Qs[rr * PAD + k0 + qid + 4];
            a[m][3] = Qs[(rr + 8) * PAD + k0 + qid + 4];
        }
#pragma unroll
        for (int n = 0; n < 8; n++) {
            const int cc = jbase + n * 8 + gid;
            const float b0 = Ks[cc * PAD + k0 + qid];
            const float b1 = Ks[cc * PAD + k0 + qid + 4];
            mma_tf32(acc[0][n], a[0], b0, b1);
            mma_tf32(acc[1][n], a[1], b0, b1);
        }
    }

    // Epilogue: add edge, store scores. c0,c1 contiguous cols -> float2.
#pragma unroll
    for (int m = 0; m < 2; m++) {
#pragma unroll
        for (int n = 0; n < 8; n++) {
            const int i = i0 + ibase + m * 16 + gid;
            const int j = j0 + jbase + n * 8 + 2 * qid;
            const size_t e0 = ((size_t)h * Lq + i) * Lq + j;
            const size_t s0 = ((size_t)bh * Lq + i) * Lq + j;
            const float2 ea = *(const float2*)(edge + e0);
            const float2 eb = *(const float2*)(edge + e0 + 8 * (size_t)Lq);
            float2 oa, ob;
            oa.x = acc[m][n][0] + ea.x; oa.y = acc[m][n][1] + ea.y;
            ob.x = acc[m][n][2] + eb.x; ob.y = acc[m][n][3] + eb.y;
            *(float2*)(out_scores + s0) = oa;
            *(float2*)(out_scores + s0 + 8 * (size_t)Lq) = ob;
        }
    }
}

// ---------------------------------------------------------------------------
// Kernel 2: masked softmax. One 256-thread block per (b,h,i) row.
// ---------------------------------------------------------------------------
__global__ __launch_bounds__(256) void softmax_kernel(
    const float* __restrict__ scores, const void* __restrict__ mask,
    float* __restrict__ wout) {
    const int row = blockIdx.x;
    const int bh = row >> 11;
    const int i  = row & (Lq - 1);
    const int b  = bh >> 4;
    const size_t soff = (size_t)row * Lq;
    const size_t moff = ((size_t)(b * Lq + i)) * Lq;
    const int tid = threadIdx.x;
    const int kind = g_mask_kind;

    const float4* sp = (const float4*)(scores + soff);
    const float4 s0 = sp[tid];
    const float4 s1 = sp[256 + tid];

    float mb[8];
    if (kind == 1) {
        const int4* mp = (const int4*)((const int*)mask + moff);
        const int4 m0 = mp[tid], m1 = mp[256 + tid];
        mb[0] = m0.x ? 1.f : 0.f; mb[1] = m0.y ? 1.f : 0.f;
        mb[2] = m0.z ? 1.f : 0.f; mb[3] = m0.w ? 1.f : 0.f;
        mb[4] = m1.x ? 1.f : 0.f; mb[5] = m1.y ? 1.f : 0.f;
        mb[6] = m1.z ? 1.f : 0.f; mb[7] = m1.w ? 1.f : 0.f;
    } else if (kind == 2) {
        const float4* mp = (const float4*)((const float*)mask + moff);
        const float4 m0 = mp[tid], m1 = mp[256 + tid];
        mb[0] = (m0.x != 0.f); mb[1] = (m0.y != 0.f);
        mb[2] = (m0.z != 0.f); mb[3] = (m0.w != 0.f);
        mb[4] = (m1.x != 0.f); mb[5] = (m1.y != 0.f);
        mb[6] = (m1.z != 0.f); mb[7] = (m1.w != 0.f);
    } else {
        const uchar4* mp = (const uchar4*)((const unsigned char*)mask + moff);
        const uchar4 m0 = mp[tid], m1 = mp[256 + tid];
        mb[0] = m0.x ? 1.f : 0.f; mb[1] = m0.y ? 1.f : 0.f;
        mb[2] = m0.z ? 1.f : 0.f; mb[3] = m0.w ? 1.f : 0.f;
        mb[4] = m1.x ? 1.f : 0.f; mb[5] = m1.y ? 1.f : 0.f;
        mb[6] = m1.z ? 1.f : 0.f; mb[7] = m1.w ? 1.f : 0.f;
    }

    const float sv[8] = {s0.x, s0.y, s0.z, s0.w, s1.x, s1.y, s1.z, s1.w};
    float x[8];
#pragma unroll
    for (int t = 0; t < 8; t++)
        x[t] = (mb[t] != 0.f) ? sv[t] * 0.125f : -1e18f;

    float mx = x[0];
#pragma unroll
    for (int t = 1; t < 8; t++) mx = fmaxf(mx, x[t]);
#pragma unroll
    for (int o = 16; o; o >>= 1) mx = fmaxf(mx, __shfl_xor_sync(0xffffffffu, mx, o));

    __shared__ float red_max[8];
    __shared__ float red_sum[8];
    if ((tid & 31) == 0) red_max[tid >> 5] = mx;
    __syncthreads();
    mx = red_max[0];
#pragma unroll
    for (int wi = 1; wi < 8; wi++) mx = fmaxf(mx, red_max[wi]);

    float e[8];
    float s = 0.0f;
#pragma unroll
    for (int t = 0; t < 8; t++) {
        e[t] = __expf(x[t] - mx);
        s += e[t];
    }
#pragma unroll
    for (int o = 16; o; o >>= 1) s += __shfl_xor_sync(0xffffffffu, s, o);
    if ((tid & 31) == 0) red_sum[tid >> 5] = s;
    __syncthreads();
    s = red_sum[0];
#pragma unroll
    for (int wi = 1; wi < 8; wi++) s += red_sum[wi];

    const float inv = 1.0f / s;
    float4 w0, w1;
    w0.x = e[0] * inv * mb[0]; w0.y = e[1] * inv * mb[1];
    w0.z = e[2] * inv * mb[2]; w0.w = e[3] * inv * mb[3];
    w1.x = e[4] * inv * mb[4]; w1.y = e[5] * inv * mb[5];
    w1.z = e[6] * inv * mb[6]; w1.w = e[7] * inv * mb[7];
    float4* wp = (float4*)(wout + soff);
    wp[tid] = w0;
    wp[256 + tid] = w1;
}

// ---------------------------------------------------------------------------
// Kernel 3: ctx[b,i,h,c] = sum_j W[b,h,i,j] * V[b,j,h,c]
// CTA: 128(i) x 64(c), K(j) chunks of 64. 8 warps 4(i) x 2(c); warp 32i x 32c.
// Ws[i][j] natural; Vt[c][j] transposed.
// ---------------------------------------------------------------------------
__global__ __launch_bounds__(256) void av_kernel(
    const float* __restrict__ w, const float* __restrict__ v,
    float* __restrict__ ctx) {
    extern __shared__ float sm[];
    float* Ws = sm;                // [128][PAD] : [i][j]
    float* Vt = sm + 128 * PAD;    // [64][PAD]  : [c][j]

    const int bh = blockIdx.y;
    const int b = bh >> 4, h = bh & 15;
    const int i0 = blockIdx.x << 7;
    const int tid = threadIdx.x;
    const int warp = tid >> 5, lane = tid & 31;
    const int wi = warp >> 1, wc = warp & 1;
    const int ibase = wi * 32, cbase = wc * 32;
    const int gid = lane >> 2, qid = lane & 3;

    float acc[2][4][4] = {};

    for (int j0 = 0; j0 < Lq; j0 += 64) {
        // W tile 128 x 64 (natural layout)
#pragma unroll
        for (int r = 0; r < 8; r++) {
            const int idx = r * 256 + tid;
            const int row = idx >> 4;
            const int j4 = (idx & 15) * 4;
            const float4 vw = *(const float4*)(w +
                ((size_t)bh * Lq + i0 + row) * Lq + j0 + j4);
            float* dst = &Ws[row * PAD + j4];
            dst[0] = f2tf(vw.x); dst[1] = f2tf(vw.y);
            dst[2] = f2tf(vw.z); dst[3] = f2tf(vw.w);
        }
        // V tile 64 x 64 transposed into Vt[c][j]
#pragma unroll
        for (int r = 0; r < 4; r++) {
            const int idx = r * 256 + tid;
            const int j = idx >> 4;
            const int c4 = (idx & 15) * 4;
            const float4 vv = *(const float4*)(v +
                ((size_t)(b * Lq + j0 + j) * Hh + h) * Cc + c4);
            Vt[(c4 + 0) * PAD + j] = f2tf(vv.x);
            Vt[(c4 + 1) * PAD + j] = f2tf(vv.y);
            Vt[(c4 + 2) * PAD + j] = f2tf(vv.z);
            Vt[(c4 + 3) * PAD + j] = f2tf(vv.w);
        }
        __syncthreads();

#pragma unroll
        for (int kk = 0; kk < 8; kk++) {
            const int k0 = kk * 8;
            float a[2][4];
#pragma unroll
            for (int m = 0; m < 2; m++) {
                const int rr = ibase + m * 16 + gid;
                a[m][0] = Ws[rr * PAD + k0 + qid];
                a[m][1] = Ws[(rr + 8) * PAD + k0 + qid];
                a[m][2] = Ws[rr * PAD + k0 + qid + 4];
                a[m][3] = Ws[(rr + 8) * PAD + k0 + qid + 4];
            }
#pragma unroll
            for (int n = 0; n < 4; n++) {
                const int cc = cbase + n * 8 + gid;
                const float b0 = Vt[cc * PAD + k0 + qid];
                const float b1 = Vt[cc * PAD + k0 + qid + 4];
                mma_tf32(acc[0][n], a[0], b0, b1);
                mma_tf32(acc[1][n], a[1], b0, b1);
            }
        }
        __syncthreads();
    }

#pragma unroll
    for (int m = 0; m < 2; m++) {
#pragma unroll
        for (int n = 0; n < 4; n++) {
            const int i = i0 + ibase + m * 16 + gid;
            const int c = h * Cc + cbase + n * 8 + 2 * qid;
            float2 oa, ob;
            oa.x = acc[m][n][0]; oa.y = acc[m][n][1];
            ob.x = acc[m][n][2]; ob.y = acc[m][n][3];
            *(float2*)(ctx + ((size_t)(b * Lq + i)) * (Hh * Cc) + c) = oa;
            *(float2*)(ctx + ((size_t)(b * Lq + i + 8)) * (Hh * Cc) + c) = ob;
        }
    }
}

// ---------------------------------------------------------------------------
extern "C" void kernel_launch(void* const* d_in, const int* in_sizes, int n_in,
                              void* d_out, int out_size) {
    (void)in_sizes; (void)n_in; (void)out_size;
    const float* q    = (const float*)d_in[0];
    const float* k    = (const float*)d_in[1];
    const float* v    = (const float*)d_in[2];
    const void*  mask = d_in[3];
    const float* edge = (const float*)d_in[4];

    float* out     = (float*)d_out;
    float* ctx     = out;
    float* scores  = out + OFF_S;
    float* weights = out + OFF_W;

    cudaFuncSetAttribute(scores_kernel,
        cudaFuncAttributeMaxDynamicSharedMemorySize, SMEM_SCORES);
    cudaFuncSetAttribute(av_kernel,
        cudaFuncAttributeMaxDynamicSharedMemorySize, SMEM_AV);

    detect_mask_kernel<<<1, 32>>>(mask);

    {
        dim3 grid(Lq / 128, Lq / 128, Bb * Hh);
        scores_kernel<<<grid, 256, SMEM_SCORES>>>(q, k, edge, scores);
    }
    {
        softmax_kernel<<<Bb * Hh * Lq, 256>>>(scores, mask, weights);
    }
    {
        dim3 grid(Lq / 128, Bb * Hh);
        av_kernel<<<grid, 256, SMEM_AV>>>(weights, v, ctx);
    }
}